// round 3
// baseline (speedup 1.0000x reference)
#include <cuda_runtime.h>
#include <cuda_bf16.h>

#define HID 128
#define MAXN 100000
#define MAXE 1600000

// Scratch (device globals — no allocation allowed)
__device__ float g_h[(size_t)MAXN * HID];    // h' = (x@W) * inv[row]
__device__ float g_agg[(size_t)MAXN * HID];  // aggregation buffer
__device__ float g_x[(size_t)MAXN * HID];    // layer activations
__device__ int   g_deg[MAXN];
__device__ float g_inv[MAXN];

// ---------------- degree / normalization ----------------
__global__ void zero_deg_kernel(int N) {
    int i = blockIdx.x * blockDim.x + threadIdx.x;
    if (i < N) g_deg[i] = 0;
}

__global__ void count_deg_kernel(const int* __restrict__ dst, int E) {
    int e = blockIdx.x * blockDim.x + threadIdx.x;
    if (e < E) atomicAdd(&g_deg[dst[e]], 1);
}

__global__ void inv_sqrt_kernel(int N) {
    int i = blockIdx.x * blockDim.x + threadIdx.x;
    if (i < N) g_inv[i] = rsqrtf((float)g_deg[i] + 1.0f);  // +1 self loop
}

// ---------------- layer GEMM: h' = (X @ W) * inv[row]; agg = h' ----------------
// block: 256 threads, tile 64 rows x 128 cols, thread tile 8x4
__global__ void gemm_layer_kernel(const float* __restrict__ X,
                                  const float* __restrict__ W,
                                  float* __restrict__ h2,
                                  float* __restrict__ agg, int N) {
    extern __shared__ float smem[];
    float* Ws = smem;              // 128*128
    float* Xs = smem + HID * HID;  // 64*128

    int tid = threadIdx.x;
    int row0 = blockIdx.x * 64;

    // load W (16384 floats) as float4
    {
        const float4* Wg = (const float4*)W;
        float4* Wsh = (float4*)Ws;
        #pragma unroll
        for (int i = tid; i < HID * HID / 4; i += 256) Wsh[i] = Wg[i];
    }
    // load 64 X rows
    {
        const float4* Xg = (const float4*)X;
        float4* Xsh = (float4*)Xs;
        #pragma unroll
        for (int i = tid; i < 64 * HID / 4; i += 256) {
            int r = i >> 5;          // i / 32 (32 float4 per row)
            int c = i & 31;
            int row = row0 + r;
            Xsh[i] = (row < N) ? Xg[(size_t)row * 32 + c]
                               : make_float4(0.f, 0.f, 0.f, 0.f);
        }
    }
    __syncthreads();

    int tx = tid & 31;   // col group -> cols tx*4 .. tx*4+3
    int ty = tid >> 5;   // row group -> rows ty*8 .. ty*8+7

    float acc[8][4];
    #pragma unroll
    for (int r = 0; r < 8; r++)
        #pragma unroll
        for (int c = 0; c < 4; c++) acc[r][c] = 0.f;

    #pragma unroll
    for (int k4 = 0; k4 < HID / 4; k4++) {
        float4 xv[8];
        #pragma unroll
        for (int r = 0; r < 8; r++)
            xv[r] = *(const float4*)&Xs[(ty * 8 + r) * HID + k4 * 4];
        #pragma unroll
        for (int kk = 0; kk < 4; kk++) {
            float4 wv = *(const float4*)&Ws[(k4 * 4 + kk) * HID + tx * 4];
            #pragma unroll
            for (int r = 0; r < 8; r++) {
                float xs = (kk == 0) ? xv[r].x : (kk == 1) ? xv[r].y
                         : (kk == 2) ? xv[r].z : xv[r].w;
                acc[r][0] = fmaf(xs, wv.x, acc[r][0]);
                acc[r][1] = fmaf(xs, wv.y, acc[r][1]);
                acc[r][2] = fmaf(xs, wv.z, acc[r][2]);
                acc[r][3] = fmaf(xs, wv.w, acc[r][3]);
            }
        }
    }

    #pragma unroll
    for (int r = 0; r < 8; r++) {
        int row = row0 + ty * 8 + r;
        if (row < N) {
            float s = g_inv[row];
            float4 v;
            v.x = acc[r][0] * s; v.y = acc[r][1] * s;
            v.z = acc[r][2] * s; v.w = acc[r][3] * s;
            *(float4*)&h2[(size_t)row * HID + tx * 4] = v;
            *(float4*)&agg[(size_t)row * HID + tx * 4] = v;  // self-loop init
        }
    }
}

// ---------------- edge scatter: agg[dst] += h'[src], warp per edge ----------------
__global__ void scatter_kernel(const int* __restrict__ src,
                               const int* __restrict__ dst,
                               const float* __restrict__ h2,
                               float* __restrict__ agg, int E) {
    int warp = (blockIdx.x * blockDim.x + threadIdx.x) >> 5;
    int lane = threadIdx.x & 31;
    if (warp >= E) return;
    int s = __ldg(src + warp);
    int d = __ldg(dst + warp);
    const float4 v = *(const float4*)(h2 + (size_t)s * HID + lane * 4);
    float* p = agg + (size_t)d * HID + lane * 4;
    asm volatile("red.global.add.v4.f32 [%0], {%1,%2,%3,%4};"
                 :: "l"(p), "f"(v.x), "f"(v.y), "f"(v.z), "f"(v.w)
                 : "memory");
}

// ---------------- x = relu(inv[row]*agg + b) ----------------
__global__ void relu_bias_kernel(const float* __restrict__ agg,
                                 const float* __restrict__ b,
                                 float* __restrict__ x, int N) {
    int i = blockIdx.x * blockDim.x + threadIdx.x;  // over N*32 float4
    if (i >= N * (HID / 4)) return;
    int row = i >> 5;
    int c4 = i & 31;
    float s = g_inv[row];
    float4 a = ((const float4*)agg)[i];
    float4 bb = ((const float4*)b)[c4];
    float4 o;
    o.x = fmaxf(fmaf(a.x, s, bb.x), 0.f);
    o.y = fmaxf(fmaf(a.y, s, bb.y), 0.f);
    o.z = fmaxf(fmaf(a.z, s, bb.z), 0.f);
    o.w = fmaxf(fmaf(a.w, s, bb.w), 0.f);
    ((float4*)x)[i] = o;
}

// ---------------- head: out = x @ W_out + b_out, warp per row ----------------
#define NCLASS 10
__global__ void out_gemm_kernel(const float* __restrict__ X,
                                const float* __restrict__ Wo,
                                const float* __restrict__ bo,
                                float* __restrict__ out, int N) {
    __shared__ float Ws[HID * NCLASS];
    __shared__ float bs[NCLASS];
    int tid = threadIdx.x;
    for (int i = tid; i < HID * NCLASS; i += blockDim.x) Ws[i] = Wo[i];
    if (tid < NCLASS) bs[tid] = bo[tid];
    __syncthreads();

    int row = blockIdx.x * 8 + (tid >> 5);
    int lane = tid & 31;
    if (row >= N) return;
    float4 xv = *(const float4*)(X + (size_t)row * HID + lane * 4);
    int k0 = lane * 4;
    #pragma unroll
    for (int c = 0; c < NCLASS; c++) {
        float p = xv.x * Ws[(k0 + 0) * NCLASS + c]
                + xv.y * Ws[(k0 + 1) * NCLASS + c]
                + xv.z * Ws[(k0 + 2) * NCLASS + c]
                + xv.w * Ws[(k0 + 3) * NCLASS + c];
        #pragma unroll
        for (int off = 16; off; off >>= 1)
            p += __shfl_down_sync(0xFFFFFFFFu, p, off);
        if (lane == 0) out[(size_t)row * NCLASS + c] = p + bs[c];
    }
}

// ---------------- launch ----------------
extern "C" void kernel_launch(void* const* d_in, const int* in_sizes, int n_in,
                              void* d_out, int out_size) {
    const int*   edge = (const int*)d_in[0];
    const float* emb  = (const float*)d_in[1];
    const float* W1   = (const float*)d_in[2];
    const float* b1   = (const float*)d_in[3];
    const float* W2   = (const float*)d_in[4];
    const float* b2   = (const float*)d_in[5];
    const float* Wo   = (const float*)d_in[6];
    const float* bo   = (const float*)d_in[7];
    float* out = (float*)d_out;

    int E = in_sizes[0] / 2;
    int N = in_sizes[1] / HID;
    const int* src = edge;
    const int* dst = edge + E;

    float *p_h, *p_agg, *p_x;
    cudaGetSymbolAddress((void**)&p_h, g_h);
    cudaGetSymbolAddress((void**)&p_agg, g_agg);
    cudaGetSymbolAddress((void**)&p_x, g_x);

    const int smem_bytes = (HID * HID + 64 * HID) * sizeof(float);  // 96KB
    cudaFuncSetAttribute(gemm_layer_kernel,
                         cudaFuncAttributeMaxDynamicSharedMemorySize, smem_bytes);

    int nb_nodes = (N + 255) / 256;
    int nb_edges = (E + 255) / 256;
    int nb_gemm = (N + 63) / 64;
    int nb_scatter = (E + 7) / 8;          // 8 warps per block, warp/edge
    int nb_elem = (N * (HID / 4) + 255) / 256;
    int nb_out = (N + 7) / 8;

    // normalization
    zero_deg_kernel<<<nb_nodes, 256>>>(N);
    count_deg_kernel<<<nb_edges, 256>>>(dst, E);
    inv_sqrt_kernel<<<nb_nodes, 256>>>(N);

    // layer 1
    gemm_layer_kernel<<<nb_gemm, 256, smem_bytes>>>(emb, W1, p_h, p_agg, N);
    scatter_kernel<<<nb_scatter, 256>>>(src, dst, p_h, p_agg, E);
    relu_bias_kernel<<<nb_elem, 256>>>(p_agg, b1, p_x, N);

    // layer 2
    gemm_layer_kernel<<<nb_gemm, 256, smem_bytes>>>(p_x, W2, p_h, p_agg, N);
    scatter_kernel<<<nb_scatter, 256>>>(src, dst, p_h, p_agg, E);
    relu_bias_kernel<<<nb_elem, 256>>>(p_agg, b2, p_x, N);

    // head
    out_gemm_kernel<<<nb_out, 256>>>(p_x, Wo, bo, out, N);
}

// round 5
// speedup vs baseline: 1.6268x; 1.6268x over previous
#include <cuda_runtime.h>
#include <cuda_bf16.h>

#define HID 128
#define MAXN 100000
#define MAXE 1600000
#define NCLASS 10

// Scratch (device globals — no allocation allowed)
__device__ float g_h[(size_t)MAXN * HID];    // h' = (x@W) * inv[row]
__device__ float g_x[(size_t)MAXN * HID];    // layer activations
__device__ int   g_deg[MAXN];                // edge in-degree (dst counts, no self)
__device__ float g_inv[MAXN];                // rsqrt(deg+1)
__device__ int   g_rowptr[MAXN];             // exclusive scan of g_deg
__device__ int   g_cursor[MAXN];             // fill cursors (reset each run)
__device__ int   g_csr[MAXE];                // src ids bucketed by dst
__device__ int   g_bsum[256];                // block partial sums for scan
__device__ int   g_boff[256];                // scanned block offsets

// ---------------- degree / normalization ----------------
__global__ void zero_deg_kernel(int N) {
    int i = blockIdx.x * blockDim.x + threadIdx.x;
    if (i < N) g_deg[i] = 0;
}

__global__ void count_deg_kernel(const int* __restrict__ dst, int E) {
    int e = blockIdx.x * blockDim.x + threadIdx.x;
    if (e < E) atomicAdd(&g_deg[dst[e]], 1);
}

__global__ void inv_sqrt_kernel(int N) {
    int i = blockIdx.x * blockDim.x + threadIdx.x;
    if (i < N) g_inv[i] = rsqrtf((float)g_deg[i] + 1.0f);  // +1 self loop
}

// ---------------- exclusive scan of g_deg -> g_rowptr (3 kernels) ----------------
// scan_local: 256 threads x 4 items = 1024 elems/block
__global__ void scan_local_kernel(int N) {
    int t = threadIdx.x;
    int lane = t & 31;
    int base = blockIdx.x * 1024 + t * 4;

    int v0 = (base + 0 < N) ? g_deg[base + 0] : 0;
    int v1 = (base + 1 < N) ? g_deg[base + 1] : 0;
    int v2 = (base + 2 < N) ? g_deg[base + 2] : 0;
    int v3 = (base + 3 < N) ? g_deg[base + 3] : 0;
    int tsum = v0 + v1 + v2 + v3;

    // inclusive warp scan of tsum
    int x = tsum;
    #pragma unroll
    for (int off = 1; off < 32; off <<= 1) {
        int y = __shfl_up_sync(0xFFFFFFFFu, x, off);
        if (lane >= off) x += y;
    }

    __shared__ int wsum[8];
    if (lane == 31) wsum[t >> 5] = x;
    __syncthreads();
    if (t == 0) {
        int a = 0;
        #pragma unroll
        for (int i = 0; i < 8; i++) { int s = wsum[i]; wsum[i] = a; a += s; }
        g_bsum[blockIdx.x] = a;  // block total
    }
    __syncthreads();

    int excl = (x - tsum) + wsum[t >> 5];
    if (base + 0 < N) g_rowptr[base + 0] = excl;
    if (base + 1 < N) g_rowptr[base + 1] = excl + v0;
    if (base + 2 < N) g_rowptr[base + 2] = excl + v0 + v1;
    if (base + 3 < N) g_rowptr[base + 3] = excl + v0 + v1 + v2;
}

// scan block sums (single block, up to 256 partials)
__global__ void scan_bsum_kernel(int NB) {
    __shared__ int sh[256];
    int t = threadIdx.x;
    int v = (t < NB) ? g_bsum[t] : 0;
    sh[t] = v;
    __syncthreads();
    #pragma unroll
    for (int off = 1; off < 256; off <<= 1) {
        int y = (t >= off) ? sh[t - off] : 0;
        __syncthreads();
        sh[t] += y;
        __syncthreads();
    }
    g_boff[t] = sh[t] - v;  // exclusive
}

// add block offsets; initialize fill cursors
__global__ void scan_add_kernel(int N) {
    int i = blockIdx.x * blockDim.x + threadIdx.x;
    if (i < N) {
        int r = g_rowptr[i] + g_boff[i >> 10];
        g_rowptr[i] = r;
        g_cursor[i] = r;
    }
}

// ---------------- CSR fill: bucket src ids by dst ----------------
__global__ void fill_csr_kernel(const int* __restrict__ src,
                                const int* __restrict__ dst, int E) {
    int e = blockIdx.x * blockDim.x + threadIdx.x;
    if (e < E) {
        int d = dst[e];
        int pos = atomicAdd(&g_cursor[d], 1);
        g_csr[pos] = src[e];
    }
}

// ---------------- layer GEMM: h' = (X @ W) * inv[row] ----------------
// block: 256 threads, tile 64 rows x 128 cols, thread tile 8x4
__global__ void gemm_layer_kernel(const float* __restrict__ X,
                                  const float* __restrict__ W,
                                  float* __restrict__ h2, int N) {
    extern __shared__ float smem[];
    float* Ws = smem;              // 128*128
    float* Xs = smem + HID * HID;  // 64*128

    int tid = threadIdx.x;
    int row0 = blockIdx.x * 64;

    {
        const float4* Wg = (const float4*)W;
        float4* Wsh = (float4*)Ws;
        #pragma unroll
        for (int i = tid; i < HID * HID / 4; i += 256) Wsh[i] = Wg[i];
    }
    {
        const float4* Xg = (const float4*)X;
        float4* Xsh = (float4*)Xs;
        #pragma unroll
        for (int i = tid; i < 64 * HID / 4; i += 256) {
            int r = i >> 5;
            int c = i & 31;
            int row = row0 + r;
            Xsh[i] = (row < N) ? Xg[(size_t)row * 32 + c]
                               : make_float4(0.f, 0.f, 0.f, 0.f);
        }
    }
    __syncthreads();

    int tx = tid & 31;   // cols tx*4 .. tx*4+3
    int ty = tid >> 5;   // rows ty*8 .. ty*8+7

    float acc[8][4];
    #pragma unroll
    for (int r = 0; r < 8; r++)
        #pragma unroll
        for (int c = 0; c < 4; c++) acc[r][c] = 0.f;

    #pragma unroll
    for (int k4 = 0; k4 < HID / 4; k4++) {
        float4 xv[8];
        #pragma unroll
        for (int r = 0; r < 8; r++)
            xv[r] = *(const float4*)&Xs[(ty * 8 + r) * HID + k4 * 4];
        #pragma unroll
        for (int kk = 0; kk < 4; kk++) {
            float4 wv = *(const float4*)&Ws[(k4 * 4 + kk) * HID + tx * 4];
            #pragma unroll
            for (int r = 0; r < 8; r++) {
                float xs = (kk == 0) ? xv[r].x : (kk == 1) ? xv[r].y
                         : (kk == 2) ? xv[r].z : xv[r].w;
                acc[r][0] = fmaf(xs, wv.x, acc[r][0]);
                acc[r][1] = fmaf(xs, wv.y, acc[r][1]);
                acc[r][2] = fmaf(xs, wv.z, acc[r][2]);
                acc[r][3] = fmaf(xs, wv.w, acc[r][3]);
            }
        }
    }

    #pragma unroll
    for (int r = 0; r < 8; r++) {
        int row = row0 + ty * 8 + r;
        if (row < N) {
            float s = g_inv[row];
            float4 v;
            v.x = acc[r][0] * s; v.y = acc[r][1] * s;
            v.z = acc[r][2] * s; v.w = acc[r][3] * s;
            *(float4*)&h2[(size_t)row * HID + tx * 4] = v;
        }
    }
}

// ---------------- fused aggregation: x[d] = relu(inv[d]*(h'[d] + sum h'[src]) + b) ----------------
// warp per destination node
__global__ void agg_relu_kernel(const float* __restrict__ h2,
                                const float* __restrict__ b,
                                float* __restrict__ x, int N) {
    int node = blockIdx.x * (blockDim.x >> 5) + (threadIdx.x >> 5);
    int lane = threadIdx.x & 31;
    if (node >= N) return;

    // self loop
    float4 acc = *(const float4*)(h2 + (size_t)node * HID + lane * 4);

    int start = g_rowptr[node];
    int cnt = g_deg[node];

    for (int e = 0; e < cnt; e += 32) {
        int s = (e + lane < cnt) ? __ldg(g_csr + start + e + lane) : 0;
        int m = min(32, cnt - e);
        for (int j = 0; j < m; j++) {
            int sj = __shfl_sync(0xFFFFFFFFu, s, j);
            const float4 v = *(const float4*)(h2 + (size_t)sj * HID + lane * 4);
            acc.x += v.x; acc.y += v.y; acc.z += v.z; acc.w += v.w;
        }
    }

    float sc = g_inv[node];
    float4 bb = ((const float4*)b)[lane];
    float4 o;
    o.x = fmaxf(fmaf(acc.x, sc, bb.x), 0.f);
    o.y = fmaxf(fmaf(acc.y, sc, bb.y), 0.f);
    o.z = fmaxf(fmaf(acc.z, sc, bb.z), 0.f);
    o.w = fmaxf(fmaf(acc.w, sc, bb.w), 0.f);
    *(float4*)(x + (size_t)node * HID + lane * 4) = o;
}

// ---------------- head: out = x @ W_out + b_out, warp per row ----------------
__global__ void out_gemm_kernel(const float* __restrict__ X,
                                const float* __restrict__ Wo,
                                const float* __restrict__ bo,
                                float* __restrict__ out, int N) {
    __shared__ float Ws[HID * NCLASS];
    __shared__ float bs[NCLASS];
    int tid = threadIdx.x;
    for (int i = tid; i < HID * NCLASS; i += blockDim.x) Ws[i] = Wo[i];
    if (tid < NCLASS) bs[tid] = bo[tid];
    __syncthreads();

    int row = blockIdx.x * 8 + (tid >> 5);
    int lane = tid & 31;
    if (row >= N) return;
    float4 xv = *(const float4*)(X + (size_t)row * HID + lane * 4);
    int k0 = lane * 4;
    #pragma unroll
    for (int c = 0; c < NCLASS; c++) {
        float p = xv.x * Ws[(k0 + 0) * NCLASS + c]
                + xv.y * Ws[(k0 + 1) * NCLASS + c]
                + xv.z * Ws[(k0 + 2) * NCLASS + c]
                + xv.w * Ws[(k0 + 3) * NCLASS + c];
        #pragma unroll
        for (int off = 16; off; off >>= 1)
            p += __shfl_down_sync(0xFFFFFFFFu, p, off);
        if (lane == 0) out[(size_t)row * NCLASS + c] = p + bs[c];
    }
}

// ---------------- launch ----------------
extern "C" void kernel_launch(void* const* d_in, const int* in_sizes, int n_in,
                              void* d_out, int out_size) {
    const int*   edge = (const int*)d_in[0];
    const float* emb  = (const float*)d_in[1];
    const float* W1   = (const float*)d_in[2];
    const float* b1   = (const float*)d_in[3];
    const float* W2   = (const float*)d_in[4];
    const float* b2   = (const float*)d_in[5];
    const float* Wo   = (const float*)d_in[6];
    const float* bo   = (const float*)d_in[7];
    float* out = (float*)d_out;

    int E = in_sizes[0] / 2;
    int N = in_sizes[1] / HID;
    const int* src = edge;
    const int* dst = edge + E;

    float *p_h, *p_x;
    cudaGetSymbolAddress((void**)&p_h, g_h);
    cudaGetSymbolAddress((void**)&p_x, g_x);

    const int smem_bytes = (HID * HID + 64 * HID) * sizeof(float);  // 96KB
    cudaFuncSetAttribute(gemm_layer_kernel,
                         cudaFuncAttributeMaxDynamicSharedMemorySize, smem_bytes);

    int nb_nodes = (N + 255) / 256;
    int nb_edges = (E + 255) / 256;
    int nb_gemm  = (N + 63) / 64;
    int nb_scan  = (N + 1023) / 1024;      // <= 98 blocks (<= 256 supported)
    int nb_agg   = (N + 7) / 8;            // 8 warps/block, warp/node
    int nb_out   = (N + 7) / 8;

    // normalization + CSR build
    zero_deg_kernel<<<nb_nodes, 256>>>(N);
    count_deg_kernel<<<nb_edges, 256>>>(dst, E);
    inv_sqrt_kernel<<<nb_nodes, 256>>>(N);
    scan_local_kernel<<<nb_scan, 256>>>(N);
    scan_bsum_kernel<<<1, 256>>>(nb_scan);
    scan_add_kernel<<<nb_nodes, 256>>>(N);
    fill_csr_kernel<<<nb_edges, 256>>>(src, dst, E);

    // layer 1
    gemm_layer_kernel<<<nb_gemm, 256, smem_bytes>>>(emb, W1, p_h, N);
    agg_relu_kernel<<<nb_agg, 256>>>(p_h, b1, p_x, N);

    // layer 2
    gemm_layer_kernel<<<nb_gemm, 256, smem_bytes>>>(p_x, W2, p_h, N);
    agg_relu_kernel<<<nb_agg, 256>>>(p_h, b2, p_x, N);

    // head
    out_gemm_kernel<<<nb_out, 256>>>(p_x, Wo, bo, out, N);
}

// round 9
// speedup vs baseline: 1.7038x; 1.0473x over previous
#include <cuda_runtime.h>
#include <cuda_bf16.h>

#define HID 128
#define MAXN 100000
#define MAXE 1600000
#define NCLASS 10

// Scratch (device globals — no allocation allowed)
__device__ float g_h[(size_t)MAXN * HID];    // h' = (x@W) * inv[row]
__device__ float g_x[(size_t)MAXN * HID];    // layer activations
__device__ int   g_deg[MAXN];                // edge in-degree (dst counts, no self)
__device__ float g_inv[MAXN];                // rsqrt(deg+1)
__device__ int   g_rowptr[MAXN];             // exclusive scan of g_deg
__device__ int   g_cursor[MAXN];             // fill cursors (reset each run)
__device__ int   g_csr[MAXE];                // src ids bucketed by dst
__device__ int   g_bsum[256];                // block partial sums for scan
__device__ int   g_boff[256];                // scanned block offsets

// ---- f32x2 packed-FMA helpers (FFMA2 — only reachable via PTX) ----
__device__ __forceinline__ unsigned long long pack_dup(float x) {
    unsigned long long p;
    asm("mov.b64 %0, {%1, %1};" : "=l"(p) : "f"(x));
    return p;
}
__device__ __forceinline__ void fma_x2(unsigned long long& d,
                                       unsigned long long a,
                                       unsigned long long b) {
    asm("fma.rn.f32x2 %0, %1, %2, %0;" : "+l"(d) : "l"(a), "l"(b));
}
__device__ __forceinline__ float2 unpack2(unsigned long long p) {
    float2 r;
    asm("mov.b64 {%0, %1}, %2;" : "=f"(r.x), "=f"(r.y) : "l"(p));
    return r;
}

// ---------------- degree / normalization ----------------
__global__ void zero_deg_kernel(int N) {
    int i = blockIdx.x * blockDim.x + threadIdx.x;
    if (i < N) g_deg[i] = 0;
}

__global__ void count_deg_kernel(const int* __restrict__ dst, int E) {
    int e = blockIdx.x * blockDim.x + threadIdx.x;
    if (e < E) atomicAdd(&g_deg[dst[e]], 1);
}

// ---------------- exclusive scan of g_deg -> g_rowptr (3 kernels) ----------------
__global__ void scan_local_kernel(int N) {
    int t = threadIdx.x;
    int lane = t & 31;
    int base = blockIdx.x * 1024 + t * 4;

    int v0 = (base + 0 < N) ? g_deg[base + 0] : 0;
    int v1 = (base + 1 < N) ? g_deg[base + 1] : 0;
    int v2 = (base + 2 < N) ? g_deg[base + 2] : 0;
    int v3 = (base + 3 < N) ? g_deg[base + 3] : 0;
    int tsum = v0 + v1 + v2 + v3;

    int x = tsum;
    #pragma unroll
    for (int off = 1; off < 32; off <<= 1) {
        int y = __shfl_up_sync(0xFFFFFFFFu, x, off);
        if (lane >= off) x += y;
    }

    __shared__ int wsum[8];
    if (lane == 31) wsum[t >> 5] = x;
    __syncthreads();
    if (t == 0) {
        int a = 0;
        #pragma unroll
        for (int i = 0; i < 8; i++) { int s = wsum[i]; wsum[i] = a; a += s; }
        g_bsum[blockIdx.x] = a;
    }
    __syncthreads();

    int excl = (x - tsum) + wsum[t >> 5];
    if (base + 0 < N) g_rowptr[base + 0] = excl;
    if (base + 1 < N) g_rowptr[base + 1] = excl + v0;
    if (base + 2 < N) g_rowptr[base + 2] = excl + v0 + v1;
    if (base + 3 < N) g_rowptr[base + 3] = excl + v0 + v1 + v2;
}

__global__ void scan_bsum_kernel(int NB) {
    __shared__ int sh[256];
    int t = threadIdx.x;
    int v = (t < NB) ? g_bsum[t] : 0;
    sh[t] = v;
    __syncthreads();
    #pragma unroll
    for (int off = 1; off < 256; off <<= 1) {
        int y = (t >= off) ? sh[t - off] : 0;
        __syncthreads();
        sh[t] += y;
        __syncthreads();
    }
    g_boff[t] = sh[t] - v;
}

// add block offsets; init cursors; compute inv_sqrt (folded in)
__global__ void scan_add_kernel(int N) {
    int i = blockIdx.x * blockDim.x + threadIdx.x;
    if (i < N) {
        int r = g_rowptr[i] + g_boff[i >> 10];
        g_rowptr[i] = r;
        g_cursor[i] = r;
        g_inv[i] = rsqrtf((float)g_deg[i] + 1.0f);  // +1 self loop
    }
}

// ---------------- CSR fill ----------------
__global__ void fill_csr_kernel(const int* __restrict__ src,
                                const int* __restrict__ dst, int E) {
    int e = blockIdx.x * blockDim.x + threadIdx.x;
    if (e < E) {
        int d = dst[e];
        int pos = atomicAdd(&g_cursor[d], 1);
        g_csr[pos] = src[e];
    }
}

// ---------------- layer GEMM: h' = (X @ W) * inv[row], FFMA2 inner loop ----------------
// block: 256 threads, tile 64 rows x 128 cols, thread tile 8x4 (as 8x2 f32x2 pairs)
__global__ void gemm_layer_kernel(const float* __restrict__ X,
                                  const float* __restrict__ W,
                                  float* __restrict__ h2, int N) {
    extern __shared__ float smem[];
    float* Ws = smem;              // 128*128
    float* Xs = smem + HID * HID;  // 64*128

    int tid = threadIdx.x;
    int row0 = blockIdx.x * 64;

    {
        const float4* Wg = (const float4*)W;
        float4* Wsh = (float4*)Ws;
        #pragma unroll
        for (int i = tid; i < HID * HID / 4; i += 256) Wsh[i] = Wg[i];
    }
    {
        const float4* Xg = (const float4*)X;
        float4* Xsh = (float4*)Xs;
        #pragma unroll
        for (int i = tid; i < 64 * HID / 4; i += 256) {
            int r = i >> 5;
            int c = i & 31;
            int row = row0 + r;
            Xsh[i] = (row < N) ? Xg[(size_t)row * 32 + c]
                               : make_float4(0.f, 0.f, 0.f, 0.f);
        }
    }
    __syncthreads();

    int tx = tid & 31;   // cols tx*4 .. tx*4+3  (2 f32x2 pairs)
    int ty = tid >> 5;   // rows ty*8 .. ty*8+7

    unsigned long long acc2[8][2];
    const unsigned long long zz = pack_dup(0.f);
    #pragma unroll
    for (int r = 0; r < 8; r++) { acc2[r][0] = zz; acc2[r][1] = zz; }

    #pragma unroll
    for (int k4 = 0; k4 < HID / 4; k4++) {
        float4 xv[8];
        #pragma unroll
        for (int r = 0; r < 8; r++)
            xv[r] = *(const float4*)&Xs[(ty * 8 + r) * HID + k4 * 4];
        #pragma unroll
        for (int kk = 0; kk < 4; kk++) {
            // W row slice as two packed f32x2 (LDS.128)
            ulonglong2 wv2 = *(const ulonglong2*)&Ws[(k4 * 4 + kk) * HID + tx * 4];
            #pragma unroll
            for (int r = 0; r < 8; r++) {
                float xs = (kk == 0) ? xv[r].x : (kk == 1) ? xv[r].y
                         : (kk == 2) ? xv[r].z : xv[r].w;
                unsigned long long xx = pack_dup(xs);
                fma_x2(acc2[r][0], xx, wv2.x);
                fma_x2(acc2[r][1], xx, wv2.y);
            }
        }
    }

    #pragma unroll
    for (int r = 0; r < 8; r++) {
        int row = row0 + ty * 8 + r;
        if (row < N) {
            float s = g_inv[row];
            float2 lo = unpack2(acc2[r][0]);
            float2 hi = unpack2(acc2[r][1]);
            float4 v;
            v.x = lo.x * s; v.y = lo.y * s;
            v.z = hi.x * s; v.w = hi.y * s;
            *(float4*)&h2[(size_t)row * HID + tx * 4] = v;
        }
    }
}

// ---------------- fused aggregation: x[d] = relu(inv[d]*(h'[d] + sum h'[src]) + b) ----------------
__global__ void agg_relu_kernel(const float* __restrict__ h2,
                                const float* __restrict__ b,
                                float* __restrict__ x, int N) {
    int node = blockIdx.x * (blockDim.x >> 5) + (threadIdx.x >> 5);
    int lane = threadIdx.x & 31;
    if (node >= N) return;

    float4 acc = *(const float4*)(h2 + (size_t)node * HID + lane * 4);  // self loop

    int start = g_rowptr[node];
    int cnt = g_deg[node];

    for (int e = 0; e < cnt; e += 32) {
        int s = (e + lane < cnt) ? __ldg(g_csr + start + e + lane) : 0;
        int m = min(32, cnt - e);
        for (int j = 0; j < m; j++) {
            int sj = __shfl_sync(0xFFFFFFFFu, s, j);
            const float4 v = *(const float4*)(h2 + (size_t)sj * HID + lane * 4);
            acc.x += v.x; acc.y += v.y; acc.z += v.z; acc.w += v.w;
        }
    }

    float sc = g_inv[node];
    float4 bb = ((const float4*)b)[lane];
    float4 o;
    o.x = fmaxf(fmaf(acc.x, sc, bb.x), 0.f);
    o.y = fmaxf(fmaf(acc.y, sc, bb.y), 0.f);
    o.z = fmaxf(fmaf(acc.z, sc, bb.z), 0.f);
    o.w = fmaxf(fmaf(acc.w, sc, bb.w), 0.f);
    *(float4*)(x + (size_t)node * HID + lane * 4) = o;
}

// ---------------- head: out = x @ W_out + b_out, warp per row ----------------
__global__ void out_gemm_kernel(const float* __restrict__ X,
                                const float* __restrict__ Wo,
                                const float* __restrict__ bo,
                                float* __restrict__ out, int N) {
    __shared__ float Ws[HID * NCLASS];
    __shared__ float bs[NCLASS];
    int tid = threadIdx.x;
    for (int i = tid; i < HID * NCLASS; i += blockDim.x) Ws[i] = Wo[i];
    if (tid < NCLASS) bs[tid] = bo[tid];
    __syncthreads();

    int row = blockIdx.x * 8 + (tid >> 5);
    int lane = tid & 31;
    if (row >= N) return;
    float4 xv = *(const float4*)(X + (size_t)row * HID + lane * 4);
    int k0 = lane * 4;
    #pragma unroll
    for (int c = 0; c < NCLASS; c++) {
        float p = xv.x * Ws[(k0 + 0) * NCLASS + c]
                + xv.y * Ws[(k0 + 1) * NCLASS + c]
                + xv.z * Ws[(k0 + 2) * NCLASS + c]
                + xv.w * Ws[(k0 + 3) * NCLASS + c];
        #pragma unroll
        for (int off = 16; off; off >>= 1)
            p += __shfl_down_sync(0xFFFFFFFFu, p, off);
        if (lane == 0) out[(size_t)row * NCLASS + c] = p + bs[c];
    }
}

// ---------------- launch ----------------
extern "C" void kernel_launch(void* const* d_in, const int* in_sizes, int n_in,
                              void* d_out, int out_size) {
    const int*   edge = (const int*)d_in[0];
    const float* emb  = (const float*)d_in[1];
    const float* W1   = (const float*)d_in[2];
    const float* b1   = (const float*)d_in[3];
    const float* W2   = (const float*)d_in[4];
    const float* b2   = (const float*)d_in[5];
    const float* Wo   = (const float*)d_in[6];
    const float* bo   = (const float*)d_in[7];
    float* out = (float*)d_out;

    int E = in_sizes[0] / 2;
    int N = in_sizes[1] / HID;
    const int* src = edge;
    const int* dst = edge + E;

    float *p_h, *p_x;
    cudaGetSymbolAddress((void**)&p_h, g_h);
    cudaGetSymbolAddress((void**)&p_x, g_x);

    const int smem_bytes = (HID * HID + 64 * HID) * sizeof(float);  // 96KB
    cudaFuncSetAttribute(gemm_layer_kernel,
                         cudaFuncAttributeMaxDynamicSharedMemorySize, smem_bytes);

    int nb_nodes = (N + 255) / 256;
    int nb_edges = (E + 255) / 256;
    int nb_gemm  = (N + 63) / 64;
    int nb_scan  = (N + 1023) / 1024;
    int nb_agg   = (N + 7) / 8;
    int nb_out   = (N + 7) / 8;

    // normalization + CSR build
    zero_deg_kernel<<<nb_nodes, 256>>>(N);
    count_deg_kernel<<<nb_edges, 256>>>(dst, E);
    scan_local_kernel<<<nb_scan, 256>>>(N);
    scan_bsum_kernel<<<1, 256>>>(nb_scan);
    scan_add_kernel<<<nb_nodes, 256>>>(N);
    fill_csr_kernel<<<nb_edges, 256>>>(src, dst, E);

    // layer 1
    gemm_layer_kernel<<<nb_gemm, 256, smem_bytes>>>(emb, W1, p_h, N);
    agg_relu_kernel<<<nb_agg, 256>>>(p_h, b1, p_x, N);

    // layer 2
    gemm_layer_kernel<<<nb_gemm, 256, smem_bytes>>>(p_x, W2, p_h, N);
    agg_relu_kernel<<<nb_agg, 256>>>(p_h, b2, p_x, N);

    // head
    out_gemm_kernel<<<nb_out, 256>>>(p_x, Wo, bo, out, N);
}

// round 11
// speedup vs baseline: 1.8640x; 1.0940x over previous
#include <cuda_runtime.h>
#include <cuda_bf16.h>
#include <cstdint>

#define HID 128
#define MAXN 100000
#define MAXE 1600000
#define NCLASS 10

// padded row stride for SMEM/gmem weight images: 136 bf16 = 272 bytes
#define WSTR 136
#define BSTR 272

// Scratch (device globals — no allocation allowed)
__device__ float g_h[(size_t)MAXN * HID];    // h' = (x@W) * inv[row]
__device__ float g_x[(size_t)MAXN * HID];    // layer activations
__device__ int   g_deg[MAXN];
__device__ float g_inv[MAXN];
__device__ int   g_rowptr[MAXN];
__device__ int   g_cursor[MAXN];
__device__ int   g_csr[MAXE];
__device__ int   g_bsum[256];
__device__ int   g_boff[256];
// W images: native [k][n] orientation, bf16 hi/lo split, padded stride WSTR
__device__ __align__(16) __nv_bfloat16 g_w1h[HID * WSTR];
__device__ __align__(16) __nv_bfloat16 g_w1l[HID * WSTR];
__device__ __align__(16) __nv_bfloat16 g_w2h[HID * WSTR];
__device__ __align__(16) __nv_bfloat16 g_w2l[HID * WSTR];

__device__ __forceinline__ uint32_t smem_u32(const void* p) {
    uint32_t a;
    asm("{ .reg .u64 t; cvta.to.shared.u64 t, %1; cvt.u32.u64 %0, t; }" : "=r"(a) : "l"(p));
    return a;
}

#define LDSM_X4(r0, r1, r2, r3, a) \
    asm volatile("ldmatrix.sync.aligned.m8n8.x4.shared.b16 {%0,%1,%2,%3}, [%4];" \
                 : "=r"(r0), "=r"(r1), "=r"(r2), "=r"(r3) : "r"(a))
#define LDSM_X4T(r0, r1, r2, r3, a) \
    asm volatile("ldmatrix.sync.aligned.m8n8.x4.trans.shared.b16 {%0,%1,%2,%3}, [%4];" \
                 : "=r"(r0), "=r"(r1), "=r"(r2), "=r"(r3) : "r"(a))
#define MMA_BF16(c, a, b) \
    asm volatile("mma.sync.aligned.m16n8k16.row.col.f32.bf16.bf16.f32 " \
                 "{%0,%1,%2,%3}, {%4,%5,%6,%7}, {%8,%9}, {%0,%1,%2,%3};" \
                 : "+f"((c)[0]), "+f"((c)[1]), "+f"((c)[2]), "+f"((c)[3]) \
                 : "r"((a)[0]), "r"((a)[1]), "r"((a)[2]), "r"((a)[3]), \
                   "r"((b)[0]), "r"((b)[1]))

// ---------------- degree / CSR build ----------------
__global__ void zero_deg_kernel(int N) {
    int i = blockIdx.x * blockDim.x + threadIdx.x;
    if (i < N) g_deg[i] = 0;
}
__global__ void count_deg_kernel(const int* __restrict__ dst, int E) {
    int e = blockIdx.x * blockDim.x + threadIdx.x;
    if (e < E) atomicAdd(&g_deg[dst[e]], 1);
}
__global__ void scan_local_kernel(int N) {
    int t = threadIdx.x;
    int lane = t & 31;
    int base = blockIdx.x * 1024 + t * 4;
    int v0 = (base + 0 < N) ? g_deg[base + 0] : 0;
    int v1 = (base + 1 < N) ? g_deg[base + 1] : 0;
    int v2 = (base + 2 < N) ? g_deg[base + 2] : 0;
    int v3 = (base + 3 < N) ? g_deg[base + 3] : 0;
    int tsum = v0 + v1 + v2 + v3;
    int x = tsum;
    #pragma unroll
    for (int off = 1; off < 32; off <<= 1) {
        int y = __shfl_up_sync(0xFFFFFFFFu, x, off);
        if (lane >= off) x += y;
    }
    __shared__ int wsum[8];
    if (lane == 31) wsum[t >> 5] = x;
    __syncthreads();
    if (t == 0) {
        int a = 0;
        #pragma unroll
        for (int i = 0; i < 8; i++) { int s = wsum[i]; wsum[i] = a; a += s; }
        g_bsum[blockIdx.x] = a;
    }
    __syncthreads();
    int excl = (x - tsum) + wsum[t >> 5];
    if (base + 0 < N) g_rowptr[base + 0] = excl;
    if (base + 1 < N) g_rowptr[base + 1] = excl + v0;
    if (base + 2 < N) g_rowptr[base + 2] = excl + v0 + v1;
    if (base + 3 < N) g_rowptr[base + 3] = excl + v0 + v1 + v2;
}
__global__ void scan_bsum_kernel(int NB) {
    __shared__ int sh[256];
    int t = threadIdx.x;
    int v = (t < NB) ? g_bsum[t] : 0;
    sh[t] = v;
    __syncthreads();
    #pragma unroll
    for (int off = 1; off < 256; off <<= 1) {
        int y = (t >= off) ? sh[t - off] : 0;
        __syncthreads();
        sh[t] += y;
        __syncthreads();
    }
    g_boff[t] = sh[t] - v;
}
__global__ void scan_add_kernel(int N) {
    int i = blockIdx.x * blockDim.x + threadIdx.x;
    if (i < N) {
        int r = g_rowptr[i] + g_boff[i >> 10];
        g_rowptr[i] = r;
        g_cursor[i] = r;
        g_inv[i] = rsqrtf((float)g_deg[i] + 1.0f);
    }
}
__global__ void fill_csr_kernel(const int* __restrict__ src,
                                const int* __restrict__ dst, int E) {
    int e = blockIdx.x * blockDim.x + threadIdx.x;
    if (e < E) {
        int d = dst[e];
        int pos = atomicAdd(&g_cursor[d], 1);
        g_csr[pos] = src[e];
    }
}

// ---------------- W prep: bf16 hi/lo split into padded [k][n] image ----------------
__global__ void prep_w_kernel(const float* __restrict__ W,
                              __nv_bfloat16* __restrict__ img_h,
                              __nv_bfloat16* __restrict__ img_l) {
    int idx = blockIdx.x * blockDim.x + threadIdx.x;  // 16384
    int k = idx >> 7;
    int n = idx & 127;
    float w = W[idx];                   // W[k][n], native orientation
    __nv_bfloat16 h = __float2bfloat16_rn(w);
    float r = w - __bfloat162float(h);
    __nv_bfloat16 l = __float2bfloat16_rn(r);
    img_h[k * WSTR + n] = h;
    img_l[k * WSTR + n] = l;
}

// ---------------- HMMA layer GEMM: h' = (X @ W) * inv[row] ----------------
// CTA 256 threads = 8 warps (4m x 2n), tile 128 rows x 128 cols, bf16x3.
#define SMA_H 0
#define SMA_L (128 * BSTR)
#define SMB_H (2 * 128 * BSTR)
#define SMB_L (3 * 128 * BSTR)
#define SM_MMA_TOTAL (4 * 128 * BSTR)   // 139264 B

__global__ void __launch_bounds__(256, 1)
gemm_mma_kernel(const float* __restrict__ X,
                const __nv_bfloat16* __restrict__ wh,
                const __nv_bfloat16* __restrict__ wl,
                float* __restrict__ h2, int N) {
    extern __shared__ char smem[];
    uint32_t sb = smem_u32(smem);
    int tid = threadIdx.x;
    int wid = tid >> 5;
    int lane = tid & 31;
    int row0 = blockIdx.x * 128;

    // copy W images (already padded) — 2 x 34KB each, float4 strided
    {
        const float4* wh4 = (const float4*)wh;
        const float4* wl4 = (const float4*)wl;
        float4* bh4 = (float4*)(smem + SMB_H);
        float4* bl4 = (float4*)(smem + SMB_L);
        const int n4 = 128 * BSTR / 16;  // 2176
        for (int i = tid; i < n4; i += 256) { bh4[i] = wh4[i]; bl4[i] = wl4[i]; }
    }

    // X tile: load fp32, split bf16 hi/lo, store padded-stride rows
    {
        const float4* Xg = (const float4*)X;
        #pragma unroll
        for (int it = 0; it < 16; it++) {
            int idx4 = it * 256 + tid;          // 4096 = 128 rows x 32 float4
            int m = idx4 >> 5;
            int c = idx4 & 31;
            int row = row0 + m;
            float4 v = (row < N) ? Xg[(size_t)row * 32 + c]
                                 : make_float4(0.f, 0.f, 0.f, 0.f);
            __nv_bfloat16 h0 = __float2bfloat16_rn(v.x);
            __nv_bfloat16 h1 = __float2bfloat16_rn(v.y);
            __nv_bfloat16 h2b = __float2bfloat16_rn(v.z);
            __nv_bfloat16 h3 = __float2bfloat16_rn(v.w);
            __nv_bfloat16 l0 = __float2bfloat16_rn(v.x - __bfloat162float(h0));
            __nv_bfloat16 l1 = __float2bfloat16_rn(v.y - __bfloat162float(h1));
            __nv_bfloat16 l2 = __float2bfloat16_rn(v.z - __bfloat162float(h2b));
            __nv_bfloat16 l3 = __float2bfloat16_rn(v.w - __bfloat162float(h3));
            __nv_bfloat162 hA = {h0, h1}, hB = {h2b, h3};
            __nv_bfloat162 lA = {l0, l1}, lB = {l2, l3};
            uint2 hp, lp;
            hp.x = *(uint32_t*)&hA; hp.y = *(uint32_t*)&hB;
            lp.x = *(uint32_t*)&lA; lp.y = *(uint32_t*)&lB;
            uint32_t off = (uint32_t)m * BSTR + (uint32_t)c * 8;
            *(uint2*)(smem + SMA_H + off) = hp;
            *(uint2*)(smem + SMA_L + off) = lp;
        }
    }
    __syncthreads();

    int wm = (wid >> 1) * 32;   // warp row offset
    int wn = (wid & 1) * 64;    // warp col offset

    float c[2][8][4];
    #pragma unroll
    for (int mt = 0; mt < 2; mt++)
        #pragma unroll
        for (int nt = 0; nt < 8; nt++)
            #pragma unroll
            for (int i = 0; i < 4; i++) c[mt][nt][i] = 0.f;

    // per-lane ldmatrix address components
    int a_row = lane & 15;                  // A: row within m16 tile
    int a_kh = (lane >> 4) << 3;            // A: k half (0/8)
    int bg = lane >> 3;
    int b_row = ((bg & 1) << 3) + (lane & 7);   // B: k row within k16
    int b_col = (bg >> 1) << 3;                 // B: n offset (0/8)

    uint32_t aH = sb + SMA_H, aL = sb + SMA_L;
    uint32_t bH = sb + SMB_H, bL = sb + SMB_L;

    #pragma unroll
    for (int kt = 0; kt < 8; kt++) {
        int k0 = kt * 16;
        uint32_t ah[2][4], al[2][4], bh[8][2], bl[8][2];
        #pragma unroll
        for (int mt = 0; mt < 2; mt++) {
            uint32_t ao = (uint32_t)(wm + mt * 16 + a_row) * BSTR + (uint32_t)(k0 + a_kh) * 2;
            LDSM_X4(ah[mt][0], ah[mt][1], ah[mt][2], ah[mt][3], aH + ao);
            LDSM_X4(al[mt][0], al[mt][1], al[mt][2], al[mt][3], aL + ao);
        }
        #pragma unroll
        for (int np = 0; np < 4; np++) {    // pairs of n8 tiles
            uint32_t bo = (uint32_t)(k0 + b_row) * BSTR + (uint32_t)(wn + np * 16 + b_col) * 2;
            LDSM_X4T(bh[np * 2][0], bh[np * 2][1], bh[np * 2 + 1][0], bh[np * 2 + 1][1], bH + bo);
            LDSM_X4T(bl[np * 2][0], bl[np * 2][1], bl[np * 2 + 1][0], bl[np * 2 + 1][1], bL + bo);
        }
        #pragma unroll
        for (int mt = 0; mt < 2; mt++)
            #pragma unroll
            for (int nt = 0; nt < 8; nt++) {
                MMA_BF16(c[mt][nt], ah[mt], bh[nt]);
                MMA_BF16(c[mt][nt], al[mt], bh[nt]);
                MMA_BF16(c[mt][nt], ah[mt], bl[nt]);
            }
    }

    // epilogue: scale by inv[row], store float2 pairs
    int r_in = lane >> 2;
    int c_in = (lane & 3) * 2;
    #pragma unroll
    for (int mt = 0; mt < 2; mt++) {
        int lr0 = wm + mt * 16 + r_in;
        int lr1 = lr0 + 8;
        int row_a = row0 + lr0;
        int row_b = row0 + lr1;
        float s0 = (row_a < N) ? g_inv[row_a] : 0.f;
        float s1 = (row_b < N) ? g_inv[row_b] : 0.f;
        #pragma unroll
        for (int nt = 0; nt < 8; nt++) {
            int col = wn + nt * 8 + c_in;
            if (row_a < N) {
                float2 v0 = {c[mt][nt][0] * s0, c[mt][nt][1] * s0};
                *(float2*)(h2 + (size_t)row_a * HID + col) = v0;
            }
            if (row_b < N) {
                float2 v1 = {c[mt][nt][2] * s1, c[mt][nt][3] * s1};
                *(float2*)(h2 + (size_t)row_b * HID + col) = v1;
            }
        }
    }
}

// ---------------- fused aggregation (unchanged) ----------------
__global__ void agg_relu_kernel(const float* __restrict__ h2,
                                const float* __restrict__ b,
                                float* __restrict__ x, int N) {
    int node = blockIdx.x * (blockDim.x >> 5) + (threadIdx.x >> 5);
    int lane = threadIdx.x & 31;
    if (node >= N) return;
    float4 acc = *(const float4*)(h2 + (size_t)node * HID + lane * 4);
    int start = g_rowptr[node];
    int cnt = g_deg[node];
    for (int e = 0; e < cnt; e += 32) {
        int s = (e + lane < cnt) ? __ldg(g_csr + start + e + lane) : 0;
        int m = min(32, cnt - e);
        for (int j = 0; j < m; j++) {
            int sj = __shfl_sync(0xFFFFFFFFu, s, j);
            const float4 v = *(const float4*)(h2 + (size_t)sj * HID + lane * 4);
            acc.x += v.x; acc.y += v.y; acc.z += v.z; acc.w += v.w;
        }
    }
    float sc = g_inv[node];
    float4 bb = ((const float4*)b)[lane];
    float4 o;
    o.x = fmaxf(fmaf(acc.x, sc, bb.x), 0.f);
    o.y = fmaxf(fmaf(acc.y, sc, bb.y), 0.f);
    o.z = fmaxf(fmaf(acc.z, sc, bb.z), 0.f);
    o.w = fmaxf(fmaf(acc.w, sc, bb.w), 0.f);
    *(float4*)(x + (size_t)node * HID + lane * 4) = o;
}

// ---------------- head (unchanged) ----------------
__global__ void out_gemm_kernel(const float* __restrict__ X,
                                const float* __restrict__ Wo,
                                const float* __restrict__ bo,
                                float* __restrict__ out, int N) {
    __shared__ float Ws[HID * NCLASS];
    __shared__ float bs[NCLASS];
    int tid = threadIdx.x;
    for (int i = tid; i < HID * NCLASS; i += blockDim.x) Ws[i] = Wo[i];
    if (tid < NCLASS) bs[tid] = bo[tid];
    __syncthreads();
    int row = blockIdx.x * 8 + (tid >> 5);
    int lane = tid & 31;
    if (row >= N) return;
    float4 xv = *(const float4*)(X + (size_t)row * HID + lane * 4);
    int k0 = lane * 4;
    #pragma unroll
    for (int c = 0; c < NCLASS; c++) {
        float p = xv.x * Ws[(k0 + 0) * NCLASS + c]
                + xv.y * Ws[(k0 + 1) * NCLASS + c]
                + xv.z * Ws[(k0 + 2) * NCLASS + c]
                + xv.w * Ws[(k0 + 3) * NCLASS + c];
        #pragma unroll
        for (int off = 16; off; off >>= 1)
            p += __shfl_down_sync(0xFFFFFFFFu, p, off);
        if (lane == 0) out[(size_t)row * NCLASS + c] = p + bs[c];
    }
}

// ---------------- launch ----------------
extern "C" void kernel_launch(void* const* d_in, const int* in_sizes, int n_in,
                              void* d_out, int out_size) {
    const int*   edge = (const int*)d_in[0];
    const float* emb  = (const float*)d_in[1];
    const float* W1   = (const float*)d_in[2];
    const float* b1   = (const float*)d_in[3];
    const float* W2   = (const float*)d_in[4];
    const float* b2   = (const float*)d_in[5];
    const float* Wo   = (const float*)d_in[6];
    const float* bo   = (const float*)d_in[7];
    float* out = (float*)d_out;

    int E = in_sizes[0] / 2;
    int N = in_sizes[1] / HID;
    const int* src = edge;
    const int* dst = edge + E;

    float *p_h, *p_x;
    __nv_bfloat16 *p_w1h, *p_w1l, *p_w2h, *p_w2l;
    cudaGetSymbolAddress((void**)&p_h, g_h);
    cudaGetSymbolAddress((void**)&p_x, g_x);
    cudaGetSymbolAddress((void**)&p_w1h, g_w1h);
    cudaGetSymbolAddress((void**)&p_w1l, g_w1l);
    cudaGetSymbolAddress((void**)&p_w2h, g_w2h);
    cudaGetSymbolAddress((void**)&p_w2l, g_w2l);

    cudaFuncSetAttribute(gemm_mma_kernel,
                         cudaFuncAttributeMaxDynamicSharedMemorySize, SM_MMA_TOTAL);

    int nb_nodes = (N + 255) / 256;
    int nb_edges = (E + 255) / 256;
    int nb_scan  = (N + 1023) / 1024;
    int nb_mma   = (N + 127) / 128;
    int nb_agg   = (N + 7) / 8;
    int nb_out   = (N + 7) / 8;

    // normalization + CSR build
    zero_deg_kernel<<<nb_nodes, 256>>>(N);
    count_deg_kernel<<<nb_edges, 256>>>(dst, E);
    scan_local_kernel<<<nb_scan, 256>>>(N);
    scan_bsum_kernel<<<1, 256>>>(nb_scan);
    scan_add_kernel<<<nb_nodes, 256>>>(N);
    fill_csr_kernel<<<nb_edges, 256>>>(src, dst, E);

    // weight prep (bf16 split + padded image)
    prep_w_kernel<<<64, 256>>>(W1, p_w1h, p_w1l);
    prep_w_kernel<<<64, 256>>>(W2, p_w2h, p_w2l);

    // layer 1
    gemm_mma_kernel<<<nb_mma, 256, SM_MMA_TOTAL>>>(emb, p_w1h, p_w1l, p_h, N);
    agg_relu_kernel<<<nb_agg, 256>>>(p_h, b1, p_x, N);

    // layer 2
    gemm_mma_kernel<<<nb_mma, 256, SM_MMA_TOTAL>>>(p_x, p_w2h, p_w2l, p_h, N);
    agg_relu_kernel<<<nb_agg, 256>>>(p_h, b2, p_x, N);

    // head
    out_gemm_kernel<<<nb_out, 256>>>(p_x, Wo, bo, out, N);
}

// round 12
// speedup vs baseline: 2.1389x; 1.1475x over previous
#include <cuda_runtime.h>
#include <cuda_bf16.h>
#include <cuda_fp16.h>
#include <cstdint>

#define HID 128
#define MAXN 100000
#define MAXE 1600000
#define NCLASS 10

// padded row stride for SMEM/gmem weight images: 136 bf16 = 272 bytes
#define WSTR 136
#define BSTR 272

// Scratch (device globals — no allocation allowed)
__device__ __half g_h[(size_t)MAXN * HID];   // h' = (x@W) * inv[row], fp16
__device__ float g_x[(size_t)MAXN * HID];    // layer activations (fp32)
__device__ int   g_deg[MAXN];
__device__ float g_inv[MAXN];
__device__ int   g_rowptr[MAXN];
__device__ int   g_cursor[MAXN];
__device__ int   g_csr[MAXE];
__device__ int   g_bsum[256];
__device__ int   g_boff[256];
// W images: native [k][n] orientation, bf16 hi/lo split, padded stride WSTR
__device__ __align__(16) __nv_bfloat16 g_w1h[HID * WSTR];
__device__ __align__(16) __nv_bfloat16 g_w1l[HID * WSTR];
__device__ __align__(16) __nv_bfloat16 g_w2h[HID * WSTR];
__device__ __align__(16) __nv_bfloat16 g_w2l[HID * WSTR];

__device__ __forceinline__ uint32_t smem_u32(const void* p) {
    uint32_t a;
    asm("{ .reg .u64 t; cvta.to.shared.u64 t, %1; cvt.u32.u64 %0, t; }" : "=r"(a) : "l"(p));
    return a;
}

#define LDSM_X4(r0, r1, r2, r3, a) \
    asm volatile("ldmatrix.sync.aligned.m8n8.x4.shared.b16 {%0,%1,%2,%3}, [%4];" \
                 : "=r"(r0), "=r"(r1), "=r"(r2), "=r"(r3) : "r"(a))
#define LDSM_X4T(r0, r1, r2, r3, a) \
    asm volatile("ldmatrix.sync.aligned.m8n8.x4.trans.shared.b16 {%0,%1,%2,%3}, [%4];" \
                 : "=r"(r0), "=r"(r1), "=r"(r2), "=r"(r3) : "r"(a))
#define MMA_BF16(c, a, b) \
    asm volatile("mma.sync.aligned.m16n8k16.row.col.f32.bf16.bf16.f32 " \
                 "{%0,%1,%2,%3}, {%4,%5,%6,%7}, {%8,%9}, {%0,%1,%2,%3};" \
                 : "+f"((c)[0]), "+f"((c)[1]), "+f"((c)[2]), "+f"((c)[3]) \
                 : "r"((a)[0]), "r"((a)[1]), "r"((a)[2]), "r"((a)[3]), \
                   "r"((b)[0]), "r"((b)[1]))

// ---------------- degree / CSR build ----------------
__global__ void zero_deg_kernel(int N) {
    int i = blockIdx.x * blockDim.x + threadIdx.x;
    if (i < N) g_deg[i] = 0;
}
__global__ void count_deg_kernel(const int* __restrict__ dst, int E) {
    int e = (blockIdx.x * blockDim.x + threadIdx.x) * 4;
    if (e + 4 <= E) {
        int4 d = *(const int4*)(dst + e);
        atomicAdd(&g_deg[d.x], 1);
        atomicAdd(&g_deg[d.y], 1);
        atomicAdd(&g_deg[d.z], 1);
        atomicAdd(&g_deg[d.w], 1);
    } else {
        for (int i = e; i < E; i++) atomicAdd(&g_deg[dst[i]], 1);
    }
}
__global__ void scan_local_kernel(int N) {
    int t = threadIdx.x;
    int lane = t & 31;
    int base = blockIdx.x * 1024 + t * 4;
    int v0 = (base + 0 < N) ? g_deg[base + 0] : 0;
    int v1 = (base + 1 < N) ? g_deg[base + 1] : 0;
    int v2 = (base + 2 < N) ? g_deg[base + 2] : 0;
    int v3 = (base + 3 < N) ? g_deg[base + 3] : 0;
    int tsum = v0 + v1 + v2 + v3;
    int x = tsum;
    #pragma unroll
    for (int off = 1; off < 32; off <<= 1) {
        int y = __shfl_up_sync(0xFFFFFFFFu, x, off);
        if (lane >= off) x += y;
    }
    __shared__ int wsum[8];
    if (lane == 31) wsum[t >> 5] = x;
    __syncthreads();
    if (t == 0) {
        int a = 0;
        #pragma unroll
        for (int i = 0; i < 8; i++) { int s = wsum[i]; wsum[i] = a; a += s; }
        g_bsum[blockIdx.x] = a;
    }
    __syncthreads();
    int excl = (x - tsum) + wsum[t >> 5];
    if (base + 0 < N) g_rowptr[base + 0] = excl;
    if (base + 1 < N) g_rowptr[base + 1] = excl + v0;
    if (base + 2 < N) g_rowptr[base + 2] = excl + v0 + v1;
    if (base + 3 < N) g_rowptr[base + 3] = excl + v0 + v1 + v2;
}
__global__ void scan_bsum_kernel(int NB) {
    __shared__ int sh[256];
    int t = threadIdx.x;
    int v = (t < NB) ? g_bsum[t] : 0;
    sh[t] = v;
    __syncthreads();
    #pragma unroll
    for (int off = 1; off < 256; off <<= 1) {
        int y = (t >= off) ? sh[t - off] : 0;
        __syncthreads();
        sh[t] += y;
        __syncthreads();
    }
    g_boff[t] = sh[t] - v;
}
__global__ void scan_add_kernel(int N) {
    int i = blockIdx.x * blockDim.x + threadIdx.x;
    if (i < N) {
        int r = g_rowptr[i] + g_boff[i >> 10];
        g_rowptr[i] = r;
        g_cursor[i] = r;
        g_inv[i] = rsqrtf((float)g_deg[i] + 1.0f);
    }
}
__global__ void fill_csr_kernel(const int* __restrict__ src,
                                const int* __restrict__ dst, int E) {
    int e = blockIdx.x * blockDim.x + threadIdx.x;
    if (e < E) {
        int d = dst[e];
        int pos = atomicAdd(&g_cursor[d], 1);
        g_csr[pos] = src[e];
    }
}

// ---------------- W prep: both weights, bf16 hi/lo split into padded [k][n] image ----------------
__global__ void prep_w_kernel(const float* __restrict__ W1,
                              const float* __restrict__ W2) {
    int g = blockIdx.x * blockDim.x + threadIdx.x;  // 32768
    int which = g >> 14;
    int idx = g & 16383;
    int k = idx >> 7;
    int n = idx & 127;
    const float* W = which ? W2 : W1;
    __nv_bfloat16* ih = which ? g_w2h : g_w1h;
    __nv_bfloat16* il = which ? g_w2l : g_w1l;
    float w = W[idx];                   // W[k][n], native orientation
    __nv_bfloat16 h = __float2bfloat16_rn(w);
    float r = w - __bfloat162float(h);
    ih[k * WSTR + n] = h;
    il[k * WSTR + n] = __float2bfloat16_rn(r);
}

// ---------------- HMMA layer GEMM: h' = (X @ W) * inv[row] -> fp16 ----------------
// CTA 256 threads = 8 warps (4m x 2n), tile 128 rows x 128 cols, bf16x3.
#define SMA_H 0
#define SMA_L (128 * BSTR)
#define SMB_H (2 * 128 * BSTR)
#define SMB_L (3 * 128 * BSTR)
#define SM_MMA_TOTAL (4 * 128 * BSTR)   // 139264 B

__global__ void __launch_bounds__(256, 1)
gemm_mma_kernel(const float* __restrict__ X,
                const __nv_bfloat16* __restrict__ wh,
                const __nv_bfloat16* __restrict__ wl,
                __half* __restrict__ h2, int N) {
    extern __shared__ char smem[];
    uint32_t sb = smem_u32(smem);
    int tid = threadIdx.x;
    int wid = tid >> 5;
    int lane = tid & 31;
    int row0 = blockIdx.x * 128;

    // copy W images (already padded) — 2 x 34KB each, float4 strided
    {
        const float4* wh4 = (const float4*)wh;
        const float4* wl4 = (const float4*)wl;
        float4* bh4 = (float4*)(smem + SMB_H);
        float4* bl4 = (float4*)(smem + SMB_L);
        const int n4 = 128 * BSTR / 16;  // 2176
        for (int i = tid; i < n4; i += 256) { bh4[i] = wh4[i]; bl4[i] = wl4[i]; }
    }

    // X tile: load fp32, split bf16 hi/lo, store padded-stride rows
    {
        const float4* Xg = (const float4*)X;
        #pragma unroll
        for (int it = 0; it < 16; it++) {
            int idx4 = it * 256 + tid;          // 4096 = 128 rows x 32 float4
            int m = idx4 >> 5;
            int c = idx4 & 31;
            int row = row0 + m;
            float4 v = (row < N) ? Xg[(size_t)row * 32 + c]
                                 : make_float4(0.f, 0.f, 0.f, 0.f);
            __nv_bfloat16 h0 = __float2bfloat16_rn(v.x);
            __nv_bfloat16 h1 = __float2bfloat16_rn(v.y);
            __nv_bfloat16 h2b = __float2bfloat16_rn(v.z);
            __nv_bfloat16 h3 = __float2bfloat16_rn(v.w);
            __nv_bfloat16 l0 = __float2bfloat16_rn(v.x - __bfloat162float(h0));
            __nv_bfloat16 l1 = __float2bfloat16_rn(v.y - __bfloat162float(h1));
            __nv_bfloat16 l2 = __float2bfloat16_rn(v.z - __bfloat162float(h2b));
            __nv_bfloat16 l3 = __float2bfloat16_rn(v.w - __bfloat162float(h3));
            __nv_bfloat162 hA = {h0, h1}, hB = {h2b, h3};
            __nv_bfloat162 lA = {l0, l1}, lB = {l2, l3};
            uint2 hp, lp;
            hp.x = *(uint32_t*)&hA; hp.y = *(uint32_t*)&hB;
            lp.x = *(uint32_t*)&lA; lp.y = *(uint32_t*)&lB;
            uint32_t off = (uint32_t)m * BSTR + (uint32_t)c * 8;
            *(uint2*)(smem + SMA_H + off) = hp;
            *(uint2*)(smem + SMA_L + off) = lp;
        }
    }
    __syncthreads();

    int wm = (wid >> 1) * 32;   // warp row offset
    int wn = (wid & 1) * 64;    // warp col offset

    float c[2][8][4];
    #pragma unroll
    for (int mt = 0; mt < 2; mt++)
        #pragma unroll
        for (int nt = 0; nt < 8; nt++)
            #pragma unroll
            for (int i = 0; i < 4; i++) c[mt][nt][i] = 0.f;

    int a_row = lane & 15;
    int a_kh = (lane >> 4) << 3;
    int bg = lane >> 3;
    int b_row = ((bg & 1) << 3) + (lane & 7);
    int b_col = (bg >> 1) << 3;

    uint32_t aH = sb + SMA_H, aL = sb + SMA_L;
    uint32_t bH = sb + SMB_H, bL = sb + SMB_L;

    #pragma unroll
    for (int kt = 0; kt < 8; kt++) {
        int k0 = kt * 16;
        uint32_t ah[2][4], al[2][4], bh[8][2], bl[8][2];
        #pragma unroll
        for (int mt = 0; mt < 2; mt++) {
            uint32_t ao = (uint32_t)(wm + mt * 16 + a_row) * BSTR + (uint32_t)(k0 + a_kh) * 2;
            LDSM_X4(ah[mt][0], ah[mt][1], ah[mt][2], ah[mt][3], aH + ao);
            LDSM_X4(al[mt][0], al[mt][1], al[mt][2], al[mt][3], aL + ao);
        }
        #pragma unroll
        for (int np = 0; np < 4; np++) {
            uint32_t bo = (uint32_t)(k0 + b_row) * BSTR + (uint32_t)(wn + np * 16 + b_col) * 2;
            LDSM_X4T(bh[np * 2][0], bh[np * 2][1], bh[np * 2 + 1][0], bh[np * 2 + 1][1], bH + bo);
            LDSM_X4T(bl[np * 2][0], bl[np * 2][1], bl[np * 2 + 1][0], bl[np * 2 + 1][1], bL + bo);
        }
        #pragma unroll
        for (int mt = 0; mt < 2; mt++)
            #pragma unroll
            for (int nt = 0; nt < 8; nt++) {
                MMA_BF16(c[mt][nt], ah[mt], bh[nt]);
                MMA_BF16(c[mt][nt], al[mt], bh[nt]);
                MMA_BF16(c[mt][nt], ah[mt], bl[nt]);
            }
    }

    // epilogue: scale by inv[row], convert to fp16, store half2 pairs
    int r_in = lane >> 2;
    int c_in = (lane & 3) * 2;
    #pragma unroll
    for (int mt = 0; mt < 2; mt++) {
        int lr0 = wm + mt * 16 + r_in;
        int lr1 = lr0 + 8;
        int row_a = row0 + lr0;
        int row_b = row0 + lr1;
        float s0 = (row_a < N) ? g_inv[row_a] : 0.f;
        float s1 = (row_b < N) ? g_inv[row_b] : 0.f;
        #pragma unroll
        for (int nt = 0; nt < 8; nt++) {
            int col = wn + nt * 8 + c_in;
            if (row_a < N) {
                __half2 v0 = __floats2half2_rn(c[mt][nt][0] * s0, c[mt][nt][1] * s0);
                *(__half2*)(h2 + (size_t)row_a * HID + col) = v0;
            }
            if (row_b < N) {
                __half2 v1 = __floats2half2_rn(c[mt][nt][2] * s1, c[mt][nt][3] * s1);
                *(__half2*)(h2 + (size_t)row_b * HID + col) = v1;
            }
        }
    }
}

// ---------------- fused aggregation over fp16 h': x[d] = relu(inv[d]*(h'[d]+sum)+b) ----------------
__global__ void agg_relu_kernel(const __half* __restrict__ h2,
                                const float* __restrict__ b,
                                float* __restrict__ x, int N) {
    int node = blockIdx.x * (blockDim.x >> 5) + (threadIdx.x >> 5);
    int lane = threadIdx.x & 31;
    if (node >= N) return;

    // self loop (4 halves per lane = 8B)
    const __half2* sp = (const __half2*)(h2 + (size_t)node * HID + lane * 4);
    float2 p0 = __half22float2(sp[0]);
    float2 p1 = __half22float2(sp[1]);
    float4 acc = {p0.x, p0.y, p1.x, p1.y};

    int start = g_rowptr[node];
    int cnt = g_deg[node];

    for (int e = 0; e < cnt; e += 32) {
        int s = (e + lane < cnt) ? __ldg(g_csr + start + e + lane) : 0;
        int m = min(32, cnt - e);
        int j = 0;
        for (; j + 1 < m; j += 2) {
            int sa = __shfl_sync(0xFFFFFFFFu, s, j);
            int sc2 = __shfl_sync(0xFFFFFFFFu, s, j + 1);
            const __half2* pa = (const __half2*)(h2 + (size_t)sa * HID + lane * 4);
            const __half2* pb = (const __half2*)(h2 + (size_t)sc2 * HID + lane * 4);
            __half2 a0 = pa[0], a1 = pa[1];
            __half2 b0 = pb[0], b1 = pb[1];
            float2 fa0 = __half22float2(a0), fa1 = __half22float2(a1);
            float2 fb0 = __half22float2(b0), fb1 = __half22float2(b1);
            acc.x += fa0.x + fb0.x; acc.y += fa0.y + fb0.y;
            acc.z += fa1.x + fb1.x; acc.w += fa1.y + fb1.y;
        }
        if (j < m) {
            int sa = __shfl_sync(0xFFFFFFFFu, s, j);
            const __half2* pa = (const __half2*)(h2 + (size_t)sa * HID + lane * 4);
            float2 fa0 = __half22float2(pa[0]);
            float2 fa1 = __half22float2(pa[1]);
            acc.x += fa0.x; acc.y += fa0.y; acc.z += fa1.x; acc.w += fa1.y;
        }
    }

    float sc = g_inv[node];
    float4 bb = ((const float4*)b)[lane];
    float4 o;
    o.x = fmaxf(fmaf(acc.x, sc, bb.x), 0.f);
    o.y = fmaxf(fmaf(acc.y, sc, bb.y), 0.f);
    o.z = fmaxf(fmaf(acc.z, sc, bb.z), 0.f);
    o.w = fmaxf(fmaf(acc.w, sc, bb.w), 0.f);
    *(float4*)(x + (size_t)node * HID + lane * 4) = o;
}

// ---------------- head: out = x @ W_out + b_out, warp per row ----------------
__global__ void out_gemm_kernel(const float* __restrict__ X,
                                const float* __restrict__ Wo,
                                const float* __restrict__ bo,
                                float* __restrict__ out, int N) {
    __shared__ float Ws[HID * NCLASS];
    __shared__ float bs[NCLASS];
    int tid = threadIdx.x;
    for (int i = tid; i < HID * NCLASS; i += blockDim.x) Ws[i] = Wo[i];
    if (tid < NCLASS) bs[tid] = bo[tid];
    __syncthreads();
    int row = blockIdx.x * 8 + (tid >> 5);
    int lane = tid & 31;
    if (row >= N) return;
    float4 xv = *(const float4*)(X + (size_t)row * HID + lane * 4);
    int k0 = lane * 4;
    #pragma unroll
    for (int c = 0; c < NCLASS; c++) {
        float p = xv.x * Ws[(k0 + 0) * NCLASS + c]
                + xv.y * Ws[(k0 + 1) * NCLASS + c]
                + xv.z * Ws[(k0 + 2) * NCLASS + c]
                + xv.w * Ws[(k0 + 3) * NCLASS + c];
        #pragma unroll
        for (int off = 16; off; off >>= 1)
            p += __shfl_down_sync(0xFFFFFFFFu, p, off);
        if (lane == 0) out[(size_t)row * NCLASS + c] = p + bs[c];
    }
}

// ---------------- launch ----------------
extern "C" void kernel_launch(void* const* d_in, const int* in_sizes, int n_in,
                              void* d_out, int out_size) {
    const int*   edge = (const int*)d_in[0];
    const float* emb  = (const float*)d_in[1];
    const float* W1   = (const float*)d_in[2];
    const float* b1   = (const float*)d_in[3];
    const float* W2   = (const float*)d_in[4];
    const float* b2   = (const float*)d_in[5];
    const float* Wo   = (const float*)d_in[6];
    const float* bo   = (const float*)d_in[7];
    float* out = (float*)d_out;

    int E = in_sizes[0] / 2;
    int N = in_sizes[1] / HID;
    const int* src = edge;
    const int* dst = edge + E;

    __half* p_h;
    float* p_x;
    __nv_bfloat16 *p_w1h, *p_w1l, *p_w2h, *p_w2l;
    cudaGetSymbolAddress((void**)&p_h, g_h);
    cudaGetSymbolAddress((void**)&p_x, g_x);
    cudaGetSymbolAddress((void**)&p_w1h, g_w1h);
    cudaGetSymbolAddress((void**)&p_w1l, g_w1l);
    cudaGetSymbolAddress((void**)&p_w2h, g_w2h);
    cudaGetSymbolAddress((void**)&p_w2l, g_w2l);

    cudaFuncSetAttribute(gemm_mma_kernel,
                         cudaFuncAttributeMaxDynamicSharedMemorySize, SM_MMA_TOTAL);

    int nb_nodes = (N + 255) / 256;
    int nb_edges = (E + 255) / 256;
    int nb_edges4 = (E / 4 + 255) / 256;
    int nb_scan  = (N + 1023) / 1024;
    int nb_mma   = (N + 127) / 128;
    int nb_agg   = (N + 7) / 8;
    int nb_out   = (N + 7) / 8;

    // normalization + CSR build
    zero_deg_kernel<<<nb_nodes, 256>>>(N);
    count_deg_kernel<<<nb_edges4, 256>>>(dst, E);
    scan_local_kernel<<<nb_scan, 256>>>(N);
    scan_bsum_kernel<<<1, 256>>>(nb_scan);
    scan_add_kernel<<<nb_nodes, 256>>>(N);
    fill_csr_kernel<<<nb_edges, 256>>>(src, dst, E);

    // weight prep (both weights in one launch)
    prep_w_kernel<<<128, 256>>>(W1, W2);

    // layer 1
    gemm_mma_kernel<<<nb_mma, 256, SM_MMA_TOTAL>>>(emb, p_w1h, p_w1l, p_h, N);
    agg_relu_kernel<<<nb_agg, 256>>>(p_h, b1, p_x, N);

    // layer 2
    gemm_mma_kernel<<<nb_mma, 256, SM_MMA_TOTAL>>>(p_x, p_w2h, p_w2l, p_h, N);
    agg_relu_kernel<<<nb_agg, 256>>>(p_h, b2, p_x, N);

    // head
    out_gemm_kernel<<<nb_out, 256>>>(p_x, Wo, bo, out, N);
}